// round 16
// baseline (speedup 1.0000x reference)
#include <cuda_runtime.h>
#include <cuda_fp16.h>
#include <cuda_bf16.h>
#include <cfloat>
#include <cstdint>

// Problem constants
#define TOK   8192
#define DIM   7168
#define NEXP  256
#define TOPKG 4
#define TOPK  8
#define RSCALE 2.5f

// Tiling: CTA covers 128(M) x 128(N); tensor group -> N [0,96), FFMA -> [96,128)
#define BM 128
#define BN 128
#define BK 32
#define NCH (DIM / BK)            // 224
#define ROWB 80                   // fp16 panel row: 32 fp16 + 16B pad
#define A_PANELB (128 * ROWB)     // 10240
#define B_PANELB (96 * ROWB)      // 7680
#define T_STAGEB (2 * A_PANELB + 2 * B_PANELB)   // 35840
#define T_SMEM (3 * T_STAGEB)     // 107520
// FFMA fp32 k-major panels
#define ASTRF 132                 // floats per k-row (128 + pad)
#define BSTRF 36                  // floats per k-row (32 + pad)
#define F_A_B (BK * ASTRF * 4)    // 16896
#define F_B_B (BK * BSTRF * 4)    // 4608
#define F_STAGEB (F_A_B + F_B_B)  // 21504
#define SMEM_BYTES (T_SMEM + 3 * F_STAGEB)       // 172032

#define NW4 ((size_t)NEXP * DIM / 4)

__device__ float g_scores[(size_t)TOK * NEXP];
__device__ uint2 g_ws[2][NW4];    // W fp16 2-way splits

// ---------------------------------------------------------------------------
// helpers
// ---------------------------------------------------------------------------
__device__ __forceinline__ uint32_t smem_u32(const void* p) {
    uint32_t a;
    asm("{ .reg .u64 t; cvta.to.shared.u64 t, %1; cvt.u32.u64 %0, t; }"
        : "=r"(a) : "l"(p));
    return a;
}
__device__ __forceinline__ void ldsm_x4(uint32_t* r, uint32_t addr) {
    asm volatile("ldmatrix.sync.aligned.m8n8.x4.shared.b16 {%0,%1,%2,%3}, [%4];"
                 : "=r"(r[0]), "=r"(r[1]), "=r"(r[2]), "=r"(r[3]) : "r"(addr));
}
__device__ __forceinline__ void ldsm_x2(uint32_t* r, uint32_t addr) {
    asm volatile("ldmatrix.sync.aligned.m8n8.x2.shared.b16 {%0,%1}, [%2];"
                 : "=r"(r[0]), "=r"(r[1]) : "r"(addr));
}
__device__ __forceinline__ void mma_f16(float* c, const uint32_t* a, const uint32_t* b) {
    asm volatile(
        "mma.sync.aligned.m16n8k16.row.col.f32.f16.f16.f32 "
        "{%0,%1,%2,%3}, {%4,%5,%6,%7}, {%8,%9}, {%0,%1,%2,%3};"
        : "+f"(c[0]), "+f"(c[1]), "+f"(c[2]), "+f"(c[3])
        : "r"(a[0]), "r"(a[1]), "r"(a[2]), "r"(a[3]), "r"(b[0]), "r"(b[1]));
}
__device__ __forceinline__ void cp_async16(uint32_t saddr, const void* g) {
    asm volatile("cp.async.cg.shared.global [%0], [%1], 16;"
                 :: "r"(saddr), "l"(g) : "memory");
}
#define CP_COMMIT() asm volatile("cp.async.commit_group;" ::: "memory")
#define CP_WAIT1()  asm volatile("cp.async.wait_group 1;" ::: "memory")
#define BARX(id, cnt) asm volatile("bar.sync %0, %1;" :: "r"(id), "r"(cnt) : "memory")

__device__ __forceinline__ uint32_t h2u(__half2 x) {
    return *reinterpret_cast<uint32_t*>(&x);
}
__device__ __forceinline__ void split2(float4 v, uint2& o0, uint2& o1) {
    __half2 p0 = __floats2half2_rn(v.x, v.y);
    __half2 p1 = __floats2half2_rn(v.z, v.w);
    float2 u0 = __half22float2(p0), u1 = __half22float2(p1);
    __half2 q0 = __floats2half2_rn(v.x - u0.x, v.y - u0.y);
    __half2 q1 = __floats2half2_rn(v.z - u1.x, v.w - u1.y);
    o0 = make_uint2(h2u(p0), h2u(p1));
    o1 = make_uint2(h2u(q0), h2u(q1));
}
__device__ __forceinline__ float sigf(float x) {
    return 1.0f / (1.0f + expf(-x));
}

// ---------------------------------------------------------------------------
// Kernel 0: W fp16 2-way splits (L2-resident in GEMM)
// ---------------------------------------------------------------------------
__global__ __launch_bounds__(256)
void splitw_kernel(const float* __restrict__ W)
{
    size_t i = (size_t)blockIdx.x * 256 + threadIdx.x;
    if (i < NW4) {
        float4 v = reinterpret_cast<const float4*>(W)[i];
        uint2 a, b;
        split2(v, a, b);
        g_ws[0][i] = a; g_ws[1][i] = b;
    }
}

// ---------------------------------------------------------------------------
// Kernel 1: dual-pipe hybrid GEMM + sigmoid + bias.
// Warps 0-7 : fp16 3-term tensor path, expert cols [n0, n0+96).
// Warps 8-15: exact fp32 FFMA path,  expert cols [n0+96, n0+128).
// Groups are fully independent (own smem regions, own named barriers).
// ---------------------------------------------------------------------------
__global__ __launch_bounds__(512, 1)
void gemm_hybrid_kernel(const float* __restrict__ X,
                        const float* __restrict__ W,
                        const float* __restrict__ bias,
                        float* __restrict__ S)
{
    extern __shared__ char sm[];
    const int tid = threadIdx.x;
    const int m0 = blockIdx.y * BM;
    const int n0 = blockIdx.x * BN;
    const uint32_t sb = smem_u32(sm);

    if (tid < 256) {
        // ================= tensor group =================
        const int wid = tid >> 5, lane = tid & 31;
        const int g = lane >> 2, tig = lane & 3;
        const int wm = wid >> 2, wn = wid & 3;     // 2(M) x 4(N); tile 64x24
        const int t8 = lane >> 3, r8 = lane & 7;
        const uint32_t a_base =
            (uint32_t)((wm * 64 + (t8 & 1) * 8 + r8) * ROWB + (t8 >> 1) * 16);
        // x2 B frag: lanes 0-7 rows, 8-15 k-halves (pattern repeats for 16-31)
        const uint32_t b_base =
            (uint32_t)((wn * 24 + (lane & 7)) * ROWB + ((lane >> 3) & 1) * 16);

        const int pr = tid >> 3, pq = tid & 7;     // A producer
        const uint32_t pa_off = (uint32_t)(pr * ROWB + pq * 8);

        float acc[4][3][4];
#pragma unroll
        for (int a = 0; a < 4; a++)
#pragma unroll
            for (int b = 0; b < 3; b++)
#pragma unroll
                for (int k = 0; k < 4; k++) acc[a][b][k] = 0.f;

        float4 RA[4];
        auto ldg_a = [&](int c) {
            const int k0 = c * BK;
#pragma unroll
            for (int i = 0; i < 4; i++)
                RA[i] = *reinterpret_cast<const float4*>(
                    X + (size_t)(m0 + pr + 32 * i) * DIM + k0 + pq * 4);
        };
        auto sts_a = [&](int s) {
            char* ab = sm + s * T_STAGEB;
#pragma unroll
            for (int i = 0; i < 4; i++) {
                uint2 o0, o1;
                split2(RA[i], o0, o1);
                const uint32_t off = pa_off + (uint32_t)(32 * i) * ROWB;
                *reinterpret_cast<uint2*>(ab + off)            = o0;
                *reinterpret_cast<uint2*>(ab + A_PANELB + off) = o1;
            }
        };
        auto cpb = [&](int c, int s) {
            const int k0 = c * BK;
            const uint32_t bb = sb + s * T_STAGEB + 2 * A_PANELB;
#pragma unroll
            for (int t = 0; t < 3; t++) {
                const int e = tid + 256 * t;       // 0..767
                const int p = (e >= 384) ? 1 : 0;
                const int s2 = e - p * 384;
                const int row = s2 >> 2, q = s2 & 3;
                cp_async16(bb + p * B_PANELB + row * ROWB + q * 16,
                           (const __half*)g_ws[p] +
                               (size_t)(n0 + row) * DIM + k0 + q * 8);
            }
        };

        ldg_a(0); sts_a(0); ldg_a(1);
        cpb(0, 0); CP_COMMIT();
        cpb(1, 1); CP_COMMIT();

        for (int c = 0; c < NCH; c++) {
            CP_WAIT1();
            BARX(1, 256);
            if (c + 1 < NCH) sts_a((c + 1) % 3);
            if (c + 2 < NCH) { ldg_a(c + 2); cpb(c + 2, (c + 2) % 3); }
            CP_COMMIT();

            const uint32_t stage = sb + (c % 3) * T_STAGEB;
            const uint32_t apan = stage;
            const uint32_t bpan = stage + 2 * A_PANELB;

#pragma unroll
            for (int half = 0; half < 2; half++) {
#pragma unroll
                for (int ks = 0; ks < 2; ks++) {
                    const uint32_t ko = (uint32_t)(ks * 32);
                    float la[2][3][4];
#pragma unroll
                    for (int a = 0; a < 2; a++)
#pragma unroll
                        for (int b = 0; b < 3; b++)
#pragma unroll
                            for (int k = 0; k < 4; k++) la[a][b][k] = 0.f;

                    uint32_t Bf[2][3][2];
#pragma unroll
                    for (int j = 0; j < 2; j++)
#pragma unroll
                        for (int nt = 0; nt < 3; nt++)
                            ldsm_x2(Bf[j][nt],
                                    bpan + (uint32_t)j * B_PANELB + b_base +
                                        nt * (8 * ROWB) + ko);
#pragma unroll
                    for (int i = 0; i < 2; i++) {
                        uint32_t Af[2][4];
#pragma unroll
                        for (int mtl = 0; mtl < 2; mtl++)
                            ldsm_x4(Af[mtl],
                                    apan + (uint32_t)i * A_PANELB + a_base +
                                        (half * 2 + mtl) * (16 * ROWB) + ko);
#pragma unroll
                        for (int j = 0; j < 2; j++) {
                            if (i + j <= 1) {   // terms h0h0, h0h1, h1h0
#pragma unroll
                                for (int mtl = 0; mtl < 2; mtl++)
#pragma unroll
                                    for (int nt = 0; nt < 3; nt++)
                                        mma_f16(la[mtl][nt], Af[mtl], Bf[j][nt]);
                            }
                        }
                    }
                    // per-kstep RN containment fold
#pragma unroll
                    for (int mtl = 0; mtl < 2; mtl++)
#pragma unroll
                        for (int nt = 0; nt < 3; nt++)
#pragma unroll
                            for (int k = 0; k < 4; k++)
                                acc[half * 2 + mtl][nt][k] += la[mtl][nt][k];
                }
            }
        }

        // epilogue (cols [n0, n0+96))
#pragma unroll
        for (int mt = 0; mt < 4; mt++) {
            const int row0 = m0 + wm * 64 + mt * 16 + g;
#pragma unroll
            for (int nt = 0; nt < 3; nt++) {
                const int ncol = n0 + wn * 24 + nt * 8 + tig * 2;
                const float b0 = bias[ncol], b1 = bias[ncol + 1];
                float2 v0, v1;
                v0.x = sigf(acc[mt][nt][0]) + b0;
                v0.y = sigf(acc[mt][nt][1]) + b1;
                v1.x = sigf(acc[mt][nt][2]) + b0;
                v1.y = sigf(acc[mt][nt][3]) + b1;
                *reinterpret_cast<float2*>(S + (size_t)row0 * NEXP + ncol) = v0;
                *reinterpret_cast<float2*>(S + (size_t)(row0 + 8) * NEXP + ncol) = v1;
            }
        }
    } else {
        // ================= FFMA group (exact fp32) =================
        const int ftid = tid - 256;
        const int fy = ftid >> 3;          // 0..31 -> rows fy*4
        const int fx = ftid & 7;           // 0..7  -> cols 96 + fx*4
        const int eB = ftid & 31, qB = ftid >> 5;   // B producer
        float* fbase = reinterpret_cast<float*>(sm + T_SMEM);

        float accf[4][4];
#pragma unroll
        for (int i = 0; i < 4; i++)
#pragma unroll
            for (int j = 0; j < 4; j++) accf[i][j] = 0.f;

        float4 RFA[4]; float4 RFB;
        auto ldg_f = [&](int c) {
            const int k0 = c * BK;
#pragma unroll
            for (int i = 0; i < 4; i++)
                RFA[i] = *reinterpret_cast<const float4*>(
                    X + (size_t)(m0 + fy + 32 * i) * DIM + k0 + fx * 4);
            RFB = *reinterpret_cast<const float4*>(
                W + (size_t)(n0 + 96 + eB) * DIM + k0 + qB * 4);
        };
        auto sts_f = [&](int s) {
            float* As = fbase + s * (F_STAGEB / 4);
            float* Bs = As + F_A_B / 4;
#pragma unroll
            for (int i = 0; i < 4; i++) {
                const float va[4] = {RFA[i].x, RFA[i].y, RFA[i].z, RFA[i].w};
#pragma unroll
                for (int j = 0; j < 4; j++)
                    As[(fx * 4 + j) * ASTRF + fy + 32 * i] = va[j];
            }
            const float vb[4] = {RFB.x, RFB.y, RFB.z, RFB.w};
#pragma unroll
            for (int j = 0; j < 4; j++)
                Bs[(qB * 4 + j) * BSTRF + eB] = vb[j];
        };

        ldg_f(0); sts_f(0); ldg_f(1);

        for (int c = 0; c < NCH; c++) {
            BARX(2, 256);
            if (c + 1 < NCH) sts_f((c + 1) % 3);
            if (c + 2 < NCH) ldg_f(c + 2);

            const float* As = fbase + (c % 3) * (F_STAGEB / 4);
            const float* Bs = As + F_A_B / 4;
#pragma unroll
            for (int k = 0; k < BK; k++) {
                const float4 a = *reinterpret_cast<const float4*>(As + k * ASTRF + fy * 4);
                const float4 b = *reinterpret_cast<const float4*>(Bs + k * BSTRF + fx * 4);
                const float av[4] = {a.x, a.y, a.z, a.w};
                const float bv[4] = {b.x, b.y, b.z, b.w};
#pragma unroll
                for (int i = 0; i < 4; i++)
#pragma unroll
                    for (int j = 0; j < 4; j++)
                        accf[i][j] = fmaf(av[i], bv[j], accf[i][j]);
            }
        }

        // epilogue (cols [n0+96, n0+128))
        const int colb = n0 + 96 + fx * 4;
        const float b0 = bias[colb], b1 = bias[colb + 1];
        const float b2 = bias[colb + 2], b3 = bias[colb + 3];
#pragma unroll
        for (int i = 0; i < 4; i++) {
            const int row = m0 + fy * 4 + i;
            float4 o;
            o.x = sigf(accf[i][0]) + b0;
            o.y = sigf(accf[i][1]) + b1;
            o.z = sigf(accf[i][2]) + b2;
            o.w = sigf(accf[i][3]) + b3;
            *reinterpret_cast<float4*>(S + (size_t)row * NEXP + colb) = o;
        }
    }
}

// ---------------------------------------------------------------------------
// Kernel 2: per-token gating (unchanged)
// ---------------------------------------------------------------------------
__global__ __launch_bounds__(256)
void gate_topk_kernel(const float* __restrict__ S,
                      float* __restrict__ outW,
                      float* __restrict__ outI)
{
    const unsigned FULL = 0xffffffffu;
    const int warp = threadIdx.x >> 5;
    const int lane = threadIdx.x & 31;
    const int token = blockIdx.x * 8 + warp;
    if (token >= TOK) return;

    float v[8];
    {
        const float4* p = reinterpret_cast<const float4*>(
            S + (size_t)token * NEXP + lane * 8);
        float4 a = p[0], b = p[1];
        v[0]=a.x; v[1]=a.y; v[2]=a.z; v[3]=a.w;
        v[4]=b.x; v[5]=b.y; v[6]=b.z; v[7]=b.w;
    }

    float m1 = -FLT_MAX, m2 = -FLT_MAX;
#pragma unroll
    for (int j = 0; j < 8; j++) {
        float x = v[j];
        if (x > m1) { m2 = m1; m1 = x; }
        else if (x > m2) { m2 = x; }
    }
#pragma unroll
    for (int off = 2; off >= 1; off >>= 1) {
        float o1 = __shfl_down_sync(FULL, m1, off, 4);
        float o2 = __shfl_down_sync(FULL, m2, off, 4);
        float n1 = fmaxf(m1, o1);
        float n2 = fmaxf(fminf(m1, o1), fmaxf(m2, o2));
        m1 = n1; m2 = n2;
    }
    float gscore = m1 + m2;

    const int myg = lane >> 2;
    float mygs = __shfl_sync(FULL, gscore, myg * 4);
    int rank = 0;
#pragma unroll
    for (int g = 0; g < 8; g++) {
        float gs = __shfl_sync(FULL, gscore, g * 4);
        if (gs > mygs || (gs == mygs && g < myg)) rank++;
    }
    bool sel = (rank < TOPKG);

    float w[8];
#pragma unroll
    for (int j = 0; j < 8; j++) w[j] = sel ? v[j] : 0.0f;

    for (int r = 0; r < TOPK; r++) {
        float bv = w[0]; int bi = lane * 8;
#pragma unroll
        for (int j = 1; j < 8; j++) {
            int idx = lane * 8 + j;
            if (w[j] > bv) { bv = w[j]; bi = idx; }
        }
#pragma unroll
        for (int o = 16; o > 0; o >>= 1) {
            float ov = __shfl_xor_sync(FULL, bv, o);
            int   oi = __shfl_xor_sync(FULL, bi, o);
            if (ov > bv || (ov == bv && oi < bi)) { bv = ov; bi = oi; }
        }
        int owner = bi >> 3;
        float orig = 0.f;
        if (lane == owner) {
            orig = v[bi & 7];
            w[bi & 7] = -FLT_MAX;
        }
        orig = __shfl_sync(FULL, orig, owner);
        if (lane == r) {
            outW[(size_t)token * TOPK + r] = orig * RSCALE;
            outI[(size_t)token * TOPK + r] = (float)bi;
        }
    }
}

// ---------------------------------------------------------------------------
extern "C" void kernel_launch(void* const* d_in, const int* in_sizes, int n_in,
                              void* d_out, int out_size)
{
    const float* x    = (const float*)d_in[0];
    const float* wght = (const float*)d_in[1];
    const float* bias = (const float*)d_in[2];
    float* out = (float*)d_out;

    float* scores;
    cudaGetSymbolAddress((void**)&scores, g_scores);

    cudaFuncSetAttribute(gemm_hybrid_kernel,
                         cudaFuncAttributeMaxDynamicSharedMemorySize, SMEM_BYTES);

    splitw_kernel<<<(int)((NW4 + 255) / 256), 256>>>(wght);

    dim3 grid(NEXP / BN, TOK / BM);
    gemm_hybrid_kernel<<<grid, 512, SMEM_BYTES>>>(x, wght, bias, scores);

    gate_topk_kernel<<<TOK / 8, 256>>>(scores, out, out + (size_t)TOK * TOPK);
}

// round 17
// speedup vs baseline: 1.7894x; 1.7894x over previous
#include <cuda_runtime.h>
#include <cuda_fp16.h>
#include <cuda_bf16.h>
#include <cfloat>
#include <cstdint>

// Problem constants
#define TOK   8192
#define DIM   7168
#define NEXP  256
#define TOPKG 4
#define TOPK  8
#define RSCALE 2.5f

// GEMM tiling: BM=64 x BN=128, 256 threads, 2 CTAs/SM
#define BM 64
#define BN 128
#define BK 32
#define NCH (DIM / BK)          // 224 K-chunks
#define NTHREADS 256            // 8 warps: 2(M) x 4(N), warp tile 32x32
#define ROWB 80                 // bytes per smem panel row: 32 fp16 + 16B pad
#define A_PANELB (64 * ROWB)    // 5120 B
#define B_PANELB (128 * ROWB)   // 10240 B
#define STAGEB (2 * A_PANELB + 2 * B_PANELB)  // 30720 B
#define NSTAGE 3
#define SMEM_BYTES (NSTAGE * STAGEB)   // 92160 B -> 2 CTAs/SM

#define NW4 ((size_t)NEXP * DIM / 4)

// scratch: bias-added sigmoid scores + precomputed W fp16 2-way splits
__device__ float g_scores[(size_t)TOK * NEXP];
__device__ uint2 g_ws[2][NW4];          // each uint2 = 4 fp16

// ---------------------------------------------------------------------------
// helpers
// ---------------------------------------------------------------------------
__device__ __forceinline__ uint32_t smem_u32(const void* p) {
    uint32_t a;
    asm("{ .reg .u64 t; cvta.to.shared.u64 t, %1; cvt.u32.u64 %0, t; }"
        : "=r"(a) : "l"(p));
    return a;
}
__device__ __forceinline__ void ldsm_x4(uint32_t* r, uint32_t addr) {
    asm volatile("ldmatrix.sync.aligned.m8n8.x4.shared.b16 {%0,%1,%2,%3}, [%4];"
                 : "=r"(r[0]), "=r"(r[1]), "=r"(r[2]), "=r"(r[3]) : "r"(addr));
}
__device__ __forceinline__ void mma_f16(float* c, const uint32_t* a, const uint32_t* b) {
    asm volatile(
        "mma.sync.aligned.m16n8k16.row.col.f32.f16.f16.f32 "
        "{%0,%1,%2,%3}, {%4,%5,%6,%7}, {%8,%9}, {%0,%1,%2,%3};"
        : "+f"(c[0]), "+f"(c[1]), "+f"(c[2]), "+f"(c[3])
        : "r"(a[0]), "r"(a[1]), "r"(a[2]), "r"(a[3]), "r"(b[0]), "r"(b[1]));
}
__device__ __forceinline__ void cp_async16(uint32_t saddr, const void* g) {
    asm volatile("cp.async.cg.shared.global [%0], [%1], 16;"
                 :: "r"(saddr), "l"(g) : "memory");
}
#define CP_COMMIT() asm volatile("cp.async.commit_group;" ::: "memory")
#define CP_WAIT1()  asm volatile("cp.async.wait_group 1;" ::: "memory")

__device__ __forceinline__ uint32_t h2u(__half2 x) {
    return *reinterpret_cast<uint32_t*>(&x);
}
// fp16 2-way split of a float4: x = h0 + h1 + r, |r| <= 2^-24 |x|
__device__ __forceinline__ void split2(float4 v, uint2& o0, uint2& o1) {
    __half2 p0 = __floats2half2_rn(v.x, v.y);
    __half2 p1 = __floats2half2_rn(v.z, v.w);
    float2 u0 = __half22float2(p0), u1 = __half22float2(p1);
    __half2 q0 = __floats2half2_rn(v.x - u0.x, v.y - u0.y);
    __half2 q1 = __floats2half2_rn(v.z - u1.x, v.w - u1.y);
    o0 = make_uint2(h2u(p0), h2u(p1));
    o1 = make_uint2(h2u(q0), h2u(q1));
}

// ---------------------------------------------------------------------------
// Kernel 0: precompute W fp16 2-way splits (11 MB -> L2-resident in GEMM)
// ---------------------------------------------------------------------------
__global__ __launch_bounds__(256)
void splitw_kernel(const float* __restrict__ W)
{
    size_t i = (size_t)blockIdx.x * 256 + threadIdx.x;
    if (i < NW4) {
        float4 v = reinterpret_cast<const float4*>(W)[i];
        uint2 a, b;
        split2(v, a, b);
        g_ws[0][i] = a; g_ws[1][i] = b;
    }
}

// ---------------------------------------------------------------------------
// Kernel 1: fp16 2-split 3-term GEMM (h0h0 + h0h1 + h1h0), per-chunk RN
// containment. BM=64 tiles, 256 threads, 2 CTAs/SM so one CTA's producer/
// sync phase overlaps the other CTA's mma phase (hides the ~150us overhead
// measured in the 1-CTA/SM version).
// ---------------------------------------------------------------------------
__global__ __launch_bounds__(NTHREADS, 2)
void gemm_mma_kernel(const float* __restrict__ X,
                     const float* __restrict__ bias,
                     float* __restrict__ S)
{
    extern __shared__ char sm[];
    const int tid  = threadIdx.x;
    const int wid  = tid >> 5, lane = tid & 31;
    const int g    = lane >> 2, tig = lane & 3;
    const int wm   = wid >> 2,  wn  = wid & 3;     // 2(M) x 4(N) warp grid
    const int m0   = blockIdx.y * BM;
    const int n0   = blockIdx.x * BN;
    const uint32_t sb = smem_u32(sm);

    // ldmatrix per-thread base offsets (within a panel)
    const int t8 = lane >> 3;
    const int r8 = lane & 7;
    const uint32_t a_base =
        (uint32_t)((wm * 32 + (t8 & 1) * 8 + r8) * ROWB + (t8 >> 1) * 16);
    const uint32_t b_base =
        (uint32_t)((wn * 32 + (t8 >> 1) * 8 + r8) * ROWB + (t8 & 1) * 16);

    // A producer coords: element e = tid (+256) -> row e>>3, float4 q = e&7
    const int pr = tid >> 3, pq = tid & 7;         // rows 0..31 (+32)
    const uint32_t pa_off = (uint32_t)(pr * ROWB + pq * 8);

    float acc[2][4][4];
#pragma unroll
    for (int i = 0; i < 2; i++)
#pragma unroll
        for (int j = 0; j < 4; j++)
#pragma unroll
            for (int k = 0; k < 4; k++) acc[i][j][k] = 0.f;

    float4 R[2];   // A LDG buffer (rows pr, pr+32)

    auto ldg_a = [&](int c) {
        const int k0 = c * BK;
        R[0] = *reinterpret_cast<const float4*>(
            X + (size_t)(m0 + pr) * DIM + k0 + pq * 4);
        R[1] = *reinterpret_cast<const float4*>(
            X + (size_t)(m0 + pr + 32) * DIM + k0 + pq * 4);
    };
    auto sts_a = [&](int s) {
        char* ab = sm + s * STAGEB;
#pragma unroll
        for (int i = 0; i < 2; i++) {
            uint2 o0, o1;
            split2(R[i], o0, o1);
            const uint32_t off = pa_off + (uint32_t)(32 * i) * ROWB;
            *reinterpret_cast<uint2*>(ab + off)            = o0;
            *reinterpret_cast<uint2*>(ab + A_PANELB + off) = o1;
        }
    };
    auto cpb = [&](int c, int s) {
        const int k0 = c * BK;
        const uint32_t st = sb + s * STAGEB + 2 * A_PANELB;
#pragma unroll
        for (int i = 0; i < 2; i++) {
            const int e   = tid + 256 * i;         // 0..511
            const int row = e >> 2, q = e & 3;     // 128 rows x 4 chunks
            const uint32_t off = (uint32_t)(row * ROWB + q * 16);
#pragma unroll
            for (int p = 0; p < 2; p++)
                cp_async16(st + p * B_PANELB + off,
                           (const __half*)g_ws[p] +
                               (size_t)(n0 + row) * DIM + k0 + q * 8);
        }
    };

    // prologue
    ldg_a(0);
    sts_a(0);
    ldg_a(1);
    cpb(0, 0); CP_COMMIT();
    cpb(1, 1); CP_COMMIT();

    for (int c = 0; c < NCH; c++) {
        CP_WAIT1();                  // B chunk c landed
        __syncthreads();             // A stores for c visible; old stages free
        if (c + 1 < NCH) sts_a((c + 1) % NSTAGE);
        if (c + 2 < NCH) { ldg_a(c + 2); cpb(c + 2, (c + 2) % NSTAGE); }
        CP_COMMIT();                 // keep FIFO group indexing

        const uint32_t stage = sb + (c % NSTAGE) * STAGEB;
        const uint32_t apan = stage;
        const uint32_t bpan = stage + 2 * A_PANELB;

        float la[2][4][4];
#pragma unroll
        for (int a = 0; a < 2; a++)
#pragma unroll
            for (int b = 0; b < 4; b++)
#pragma unroll
                for (int k = 0; k < 4; k++) la[a][b][k] = 0.f;

#pragma unroll
        for (int ks = 0; ks < 2; ks++) {
            const uint32_t ko = (uint32_t)(ks * 32);
            uint32_t Bf[2][2][4];
#pragma unroll
            for (int j = 0; j < 2; j++)
#pragma unroll
                for (int p = 0; p < 2; p++)
                    ldsm_x4(Bf[j][p],
                            bpan + (uint32_t)j * B_PANELB + b_base + p * (16 * ROWB) + ko);

#pragma unroll
            for (int i = 0; i < 2; i++) {
                uint32_t Af[2][4];
#pragma unroll
                for (int mt = 0; mt < 2; mt++)
                    ldsm_x4(Af[mt],
                            apan + (uint32_t)i * A_PANELB + a_base + mt * (16 * ROWB) + ko);
#pragma unroll
                for (int j = 0; j < 2; j++) {
                    if (i + j <= 1) {      // 3 terms: h0h0, h0h1, h1h0
#pragma unroll
                        for (int mt = 0; mt < 2; mt++)
#pragma unroll
                            for (int nt = 0; nt < 4; nt++)
                                mma_f16(la[mt][nt], Af[mt],
                                        &Bf[j][nt >> 1][(nt & 1) * 2]);
                    }
                }
            }
        }
        // RN fold (containment of TC rounding)
#pragma unroll
        for (int mt = 0; mt < 2; mt++)
#pragma unroll
            for (int nt = 0; nt < 4; nt++)
#pragma unroll
                for (int k = 0; k < 4; k++)
                    acc[mt][nt][k] += la[mt][nt][k];
    }

    // ---- epilogue: sigmoid + bias -> S
#pragma unroll
    for (int mt = 0; mt < 2; mt++) {
        const int row0 = m0 + wm * 32 + mt * 16 + g;
#pragma unroll
        for (int nt = 0; nt < 4; nt++) {
            const int ncol = n0 + wn * 32 + nt * 8 + tig * 2;
            const float b0 = bias[ncol], b1 = bias[ncol + 1];
            float2 v0, v1;
            v0.x = 1.0f / (1.0f + expf(-acc[mt][nt][0])) + b0;
            v0.y = 1.0f / (1.0f + expf(-acc[mt][nt][1])) + b1;
            v1.x = 1.0f / (1.0f + expf(-acc[mt][nt][2])) + b0;
            v1.y = 1.0f / (1.0f + expf(-acc[mt][nt][3])) + b1;
            *reinterpret_cast<float2*>(S + (size_t)row0 * NEXP + ncol) = v0;
            *reinterpret_cast<float2*>(S + (size_t)(row0 + 8) * NEXP + ncol) = v1;
        }
    }
}

// ---------------------------------------------------------------------------
// Kernel 2: per-token gating (unchanged)
// ---------------------------------------------------------------------------
__global__ __launch_bounds__(256)
void gate_topk_kernel(const float* __restrict__ S,
                      float* __restrict__ outW,
                      float* __restrict__ outI)
{
    const unsigned FULL = 0xffffffffu;
    const int warp = threadIdx.x >> 5;
    const int lane = threadIdx.x & 31;
    const int token = blockIdx.x * 8 + warp;
    if (token >= TOK) return;

    float v[8];
    {
        const float4* p = reinterpret_cast<const float4*>(
            S + (size_t)token * NEXP + lane * 8);
        float4 a = p[0], b = p[1];
        v[0]=a.x; v[1]=a.y; v[2]=a.z; v[3]=a.w;
        v[4]=b.x; v[5]=b.y; v[6]=b.z; v[7]=b.w;
    }

    float m1 = -FLT_MAX, m2 = -FLT_MAX;
#pragma unroll
    for (int j = 0; j < 8; j++) {
        float x = v[j];
        if (x > m1) { m2 = m1; m1 = x; }
        else if (x > m2) { m2 = x; }
    }
#pragma unroll
    for (int off = 2; off >= 1; off >>= 1) {
        float o1 = __shfl_down_sync(FULL, m1, off, 4);
        float o2 = __shfl_down_sync(FULL, m2, off, 4);
        float n1 = fmaxf(m1, o1);
        float n2 = fmaxf(fminf(m1, o1), fmaxf(m2, o2));
        m1 = n1; m2 = n2;
    }
    float gscore = m1 + m2;

    const int myg = lane >> 2;
    float mygs = __shfl_sync(FULL, gscore, myg * 4);
    int rank = 0;
#pragma unroll
    for (int g = 0; g < 8; g++) {
        float gs = __shfl_sync(FULL, gscore, g * 4);
        if (gs > mygs || (gs == mygs && g < myg)) rank++;
    }
    bool sel = (rank < TOPKG);

    float w[8];
#pragma unroll
    for (int j = 0; j < 8; j++) w[j] = sel ? v[j] : 0.0f;

    for (int r = 0; r < TOPK; r++) {
        float bv = w[0]; int bi = lane * 8;
#pragma unroll
        for (int j = 1; j < 8; j++) {
            int idx = lane * 8 + j;
            if (w[j] > bv) { bv = w[j]; bi = idx; }
        }
#pragma unroll
        for (int o = 16; o > 0; o >>= 1) {
            float ov = __shfl_xor_sync(FULL, bv, o);
            int   oi = __shfl_xor_sync(FULL, bi, o);
            if (ov > bv || (ov == bv && oi < bi)) { bv = ov; bi = oi; }
        }
        int owner = bi >> 3;
        float orig = 0.f;
        if (lane == owner) {
            orig = v[bi & 7];
            w[bi & 7] = -FLT_MAX;
        }
        orig = __shfl_sync(FULL, orig, owner);
        if (lane == r) {
            outW[(size_t)token * TOPK + r] = orig * RSCALE;
            outI[(size_t)token * TOPK + r] = (float)bi;
        }
    }
}

// ---------------------------------------------------------------------------
extern "C" void kernel_launch(void* const* d_in, const int* in_sizes, int n_in,
                              void* d_out, int out_size)
{
    const float* x    = (const float*)d_in[0];
    const float* wght = (const float*)d_in[1];
    const float* bias = (const float*)d_in[2];
    float* out = (float*)d_out;

    float* scores;
    cudaGetSymbolAddress((void**)&scores, g_scores);

    cudaFuncSetAttribute(gemm_mma_kernel,
                         cudaFuncAttributeMaxDynamicSharedMemorySize, SMEM_BYTES);

    splitw_kernel<<<(int)((NW4 + 255) / 256), 256>>>(wght);

    dim3 grid(NEXP / BN, TOK / BM);
    gemm_mma_kernel<<<grid, NTHREADS, SMEM_BYTES>>>(x, bias, scores);

    gate_topk_kernel<<<TOK / 8, 256>>>(scores, out, out + (size_t)TOK * TOPK);
}